// round 6
// baseline (speedup 1.0000x reference)
#include <cuda_runtime.h>
#include <climits>

// DTM layer via two-level weighted histogram quantile localization.
// Level-1: 8-way bank-interleaved replicated histogram + register pair-merge.
// Level-2: fused fine-histogram + value-histogram (d2*w) + below-lo partial
// sums, so no third data pass is needed. All histogram sums are integer
// (weights x 2^19, d2*w x 2^40) -> fully deterministic.

constexpr int   NPTS    = 4096;           // points per batch (H*W)
constexpr int   THREADS = 256;
constexpr int   PPT     = NPTS / THREADS; // 16 points/thread, register-resident
constexpr int   NW      = THREADS / 32;
constexpr int   NB      = 128;            // bins per level
constexpr int   REP     = 8;              // level-1 replicas (bank-interleaved)
constexpr float M0F     = 0.3f;
constexpr float RANGE   = 12.0f;          // safe upper bound on d2
constexpr float SCALE   = 524288.0f;          // 2^19 weight quantizer
constexpr float INV_SCALE  = 1.0f / 524288.0f;
constexpr float SW_SCALE   = 2097152.0f;      // 2^21: d2*wi*2^21 = d2*w*2^40
constexpr float INV_SCALE2 = 9.094947017729282e-13f;  // 2^-40

__device__ __forceinline__ float warp_sum(float v) {
    #pragma unroll
    for (int o = 16; o > 0; o >>= 1) v += __shfl_xor_sync(0xffffffffu, v, o);
    return v;
}

__global__ void __launch_bounds__(THREADS, 4) dtm_kernel(
    const float* __restrict__ input,   // (B, N, 2)
    const float* __restrict__ weight,  // (B, N)
    const float* __restrict__ grid,    // (N, 2)
    float* __restrict__ out)           // (B, N)
{
    __shared__ unsigned hist1[NB * REP];          // level-1, word-interleaved
    __shared__ unsigned hist2[NB];                // level-2 weight histogram
    __shared__ unsigned long long hist2w[NB];     // level-2 d2*w histogram
    __shared__ unsigned wtot[4];                  // scan totals (4 scan warps)
    __shared__ int      cbin[4];
    __shared__ unsigned ccum[4];
    __shared__ float    redS[NW];
    __shared__ unsigned long long wtot64[4];

    const int blk  = blockIdx.x;              // b * NPTS + q
    const int b    = blk >> 12;                // NPTS == 4096
    const int q    = blk & (NPTS - 1);
    const int t    = threadIdx.x;
    const int lane = t & 31, wid = t >> 5;
    const int rep  = lane & (REP - 1);

    const float gx = __ldg(&grid[2 * q]);
    const float gy = __ldg(&grid[2 * q + 1]);

    const float4* __restrict__ pts4 =
        reinterpret_cast<const float4*>(input + (size_t)b * NPTS * 2);
    const float2* __restrict__ wgt2 =
        reinterpret_cast<const float2*>(weight + (size_t)b * NPTS);

    // Load 16 points/thread as 8 x float4 (2 points each) + 8 x float2 weights.
    float    d2[PPT];
    unsigned wi[PPT];
    #pragma unroll
    for (int k = 0; k < PPT / 2; k++) {
        const int u = t + k * THREADS;         // float4 index -> points 2u, 2u+1
        const float4 p = pts4[u];
        const float2 w = wgt2[u];
        float dx = p.x - gx, dy = p.y - gy;
        d2[2 * k]     = fmaf(dx, dx, dy * dy);
        dx = p.z - gx; dy = p.w - gy;
        d2[2 * k + 1] = fmaf(dx, dx, dy * dy);
        wi[2 * k]     = (unsigned)(w.x * SCALE);
        wi[2 * k + 1] = (unsigned)(w.y * SCALE);
    }

    // Zero histograms: 1024 + 128 + 128(u64) words.
    #pragma unroll
    for (int i = 0; i < (NB * REP) / THREADS; i++) hist1[t + i * THREADS] = 0u;
    if (t < NB) { hist2[t] = 0u; hist2w[t] = 0ull; }
    __syncthreads();

    // ============ Level 1: replicated weighted histogram ============
    {
        const float inv1 = (float)NB / RANGE;
        #pragma unroll
        for (int k = 0; k < PPT; k += 2) {
            int b0 = min(__float2int_rz(d2[k]     * inv1), NB - 1);
            int b1 = min(__float2int_rz(d2[k + 1] * inv1), NB - 1);
            if (b0 == b1) {                    // adjacent points: usually same bin
                atomicAdd(&hist1[b0 * REP + rep], wi[k] + wi[k + 1]);
            } else {
                atomicAdd(&hist1[b0 * REP + rep], wi[k]);
                atomicAdd(&hist1[b1 * REP + rep], wi[k + 1]);
            }
        }
    }
    __syncthreads();

    // Scan level-1 histogram (threads 0..127), then find crossing bin.
    unsigned v1 = 0, h1 = 0;
    if (t < NB) {
        #pragma unroll
        for (int r = 0; r < REP; r++) h1 += hist1[t * REP + r];
        v1 = h1;                               // warp-inclusive scan
        #pragma unroll
        for (int o = 1; o < 32; o <<= 1) {
            const unsigned n = __shfl_up_sync(0xffffffffu, v1, o);
            if (lane >= o) v1 += n;
        }
        if (lane == 31) wtot[wid] = v1;
    }
    __syncthreads();

    const unsigned total = wtot[0] + wtot[1] + wtot[2] + wtot[3];
    unsigned target = (unsigned)(M0F * (float)total);

    if (t < NB) {
        unsigned off = 0;
        #pragma unroll
        for (int i = 0; i < 4; i++) if (i < wid) off += wtot[i];
        const unsigned cum = v1 + off;         // global inclusive prefix
        const unsigned bal = __ballot_sync(0xffffffffu, cum >= target);
        if (bal) {
            if (lane == __ffs(bal) - 1) { cbin[wid] = t; ccum[wid] = cum - h1; }
        } else if (lane == 0) {
            cbin[wid] = INT_MAX; ccum[wid] = 0u;
        }
    }
    __syncthreads();

    int bsel; unsigned csel;
    {
        bsel = cbin[0]; csel = ccum[0];
        if (cbin[1] < bsel) { bsel = cbin[1]; csel = ccum[1]; }
        if (cbin[2] < bsel) { bsel = cbin[2]; csel = ccum[2]; }
        if (cbin[3] < bsel) { bsel = cbin[3]; csel = ccum[3]; }
        if (bsel > NB - 1) bsel = NB - 1;
    }
    target -= csel;                            // remaining mass inside coarse bin
    const float lo = (float)bsel * (RANGE / NB);
    __syncthreads();                           // wtot/cbin/ccum reuse in level 2

    // ==== Level 2 (fused): fine histograms + below-lo partial sums ====
    // Points below lo accumulate S directly; points in [lo, lo+RANGE/NB) feed
    // both the weight histogram and the d2*w value histogram (u64, exact).
    float Slo = 0.f;
    {
        const float inv2 = (float)NB * (float)NB / RANGE;
        #pragma unroll
        for (int k = 0; k < PPT; k++) {
            const float diff = d2[k] - lo;
            const float wf = (float)wi[k];     // quantized weight as float
            if (diff < 0.f) {
                Slo = fmaf(d2[k], wf * INV_SCALE, Slo);
            } else {
                const int bin = __float2int_rd(diff * inv2);
                if (bin < NB) {
                    atomicAdd(&hist2[bin], wi[k]);
                    atomicAdd(&hist2w[bin],
                              (unsigned long long)(d2[k] * wf * SW_SCALE));
                }
            }
        }
    }
    {
        const float rs = warp_sum(Slo);
        if (lane == 0) redS[wid] = rs;
    }
    __syncthreads();

    // Scan level-2 histogram, find fine crossing bin.
    unsigned v2 = 0, h2 = 0;
    if (t < NB) {
        h2 = hist2[t];
        v2 = h2;
        #pragma unroll
        for (int o = 1; o < 32; o <<= 1) {
            const unsigned n = __shfl_up_sync(0xffffffffu, v2, o);
            if (lane >= o) v2 += n;
        }
        if (lane == 31) wtot[wid] = v2;
    }
    __syncthreads();

    if (t < NB) {
        unsigned off = 0;
        #pragma unroll
        for (int i = 0; i < 4; i++) if (i < wid) off += wtot[i];
        const unsigned cum = v2 + off;
        const unsigned bal = __ballot_sync(0xffffffffu, cum >= target);
        if (bal) {
            if (lane == __ffs(bal) - 1) { cbin[wid] = t; ccum[wid] = cum - h2; }
        } else if (lane == 0) {
            cbin[wid] = INT_MAX; ccum[wid] = 0u;
        }
    }
    __syncthreads();

    int bsel2; unsigned csel2;
    {
        bsel2 = cbin[0]; csel2 = ccum[0];
        if (cbin[1] < bsel2) { bsel2 = cbin[1]; csel2 = ccum[1]; }
        if (cbin[2] < bsel2) { bsel2 = cbin[2]; csel2 = ccum[2]; }
        if (cbin[3] < bsel2) { bsel2 = cbin[3]; csel2 = ccum[3]; }
        if (bsel2 > NB - 1) bsel2 = NB - 1;
    }

    // Predicated block reduce of hist2w prefix (bins strictly below bsel2).
    unsigned long long ps = 0ull;
    if (t < NB && t < bsel2) ps = hist2w[t];
    #pragma unroll
    for (int o = 16; o > 0; o >>= 1) ps += __shfl_xor_sync(0xffffffffu, ps, o);
    if (t < NB && lane == 0) wtot64[wid] = ps;
    __syncthreads();

    if (t == 0) {
        float S = 0.f;
        #pragma unroll
        for (int i = 0; i < NW; i++) S += redS[i];
        const unsigned long long pre = wtot64[0] + wtot64[1] + wtot64[2] + wtot64[3];
        S += (float)pre * INV_SCALE2;
        // S, W are exact partial sums strictly below tau = start of fine bin.
        const float W   = (float)(csel + csel2) * INV_SCALE;
        const float wb  = M0F * ((float)total * INV_SCALE);
        const float tau = lo + (float)bsel2 * (RANGE / (NB * NB));
        const float val = S + tau * (wb - W);
        out[blk] = sqrtf(fmaxf(val, 0.f) / wb);
    }
}

extern "C" void kernel_launch(void* const* d_in, const int* in_sizes, int n_in,
                              void* d_out, int out_size) {
    const float* input  = (const float*)d_in[0];   // (B, N, 2)
    const float* weight = (const float*)d_in[1];   // (B, N)
    const float* grid   = (const float*)d_in[2];   // (N, 2)
    float* out = (float*)d_out;                    // (B, N)

    const int total = in_sizes[1];                 // B * N queries (= out_size)
    dtm_kernel<<<total, THREADS>>>(input, weight, grid, out);
}

// round 7
// speedup vs baseline: 1.3987x; 1.3987x over previous
#include <cuda_runtime.h>
#include <climits>

// DTM layer via two-level weighted histogram quantile localization.
// (R5 skeleton: best verified at 57.8us.) Deltas: REP=8 replicas on level-1
// and branchless pair-merge (predicated second atomic instead of if/else).
// Weights quantized to u32 (x 2^19): deterministic integer histogram sums.

constexpr int   NPTS    = 4096;           // points per batch (H*W)
constexpr int   THREADS = 256;
constexpr int   PPT     = NPTS / THREADS; // 16 points/thread, register-resident
constexpr int   NW      = THREADS / 32;
constexpr int   NB      = 128;            // bins per level
constexpr int   REP     = 8;              // level-1 replicas (bank-interleaved)
constexpr float M0F     = 0.3f;
constexpr float RANGE   = 12.0f;          // safe upper bound on d2
constexpr float SCALE   = 524288.0f;      // 2^19: sum < 4096*2^19 = 2^31
constexpr float INV_SCALE = 1.0f / 524288.0f;

__device__ __forceinline__ float warp_sum(float v) {
    #pragma unroll
    for (int o = 16; o > 0; o >>= 1) v += __shfl_xor_sync(0xffffffffu, v, o);
    return v;
}

__global__ void __launch_bounds__(THREADS, 4) dtm_kernel(
    const float* __restrict__ input,   // (B, N, 2)
    const float* __restrict__ weight,  // (B, N)
    const float* __restrict__ grid,    // (N, 2)
    float* __restrict__ out)           // (B, N)
{
    __shared__ unsigned hist1[NB * REP];  // [bin][replica], word-interleaved
    __shared__ unsigned hist2[NB];
    __shared__ unsigned wtot[4];          // scan totals (4 scan warps)
    __shared__ int      cbin[4];
    __shared__ unsigned ccum[4];
    __shared__ float    redS[NW], redW[NW];

    const int blk  = blockIdx.x;              // b * NPTS + q
    const int b    = blk >> 12;                // NPTS == 4096
    const int q    = blk & (NPTS - 1);
    const int t    = threadIdx.x;
    const int lane = t & 31, wid = t >> 5;
    const int rep  = lane & (REP - 1);

    const float gx = __ldg(&grid[2 * q]);
    const float gy = __ldg(&grid[2 * q + 1]);

    const float4* __restrict__ pts4 =
        reinterpret_cast<const float4*>(input + (size_t)b * NPTS * 2);
    const float2* __restrict__ wgt2 =
        reinterpret_cast<const float2*>(weight + (size_t)b * NPTS);

    // Load 16 points/thread as 8 x float4 (2 points each) + 8 x float2 weights.
    float    d2[PPT];
    unsigned wi[PPT];
    #pragma unroll
    for (int k = 0; k < PPT / 2; k++) {
        const int u = t + k * THREADS;         // float4 index -> points 2u, 2u+1
        const float4 p = pts4[u];
        const float2 w = wgt2[u];
        float dx = p.x - gx, dy = p.y - gy;
        d2[2 * k]     = fmaf(dx, dx, dy * dy);
        dx = p.z - gx; dy = p.w - gy;
        d2[2 * k + 1] = fmaf(dx, dx, dy * dy);
        wi[2 * k]     = (unsigned)(w.x * SCALE);
        wi[2 * k + 1] = (unsigned)(w.y * SCALE);
    }

    // Zero histograms: 1024 + 128 words, 256 threads.
    #pragma unroll
    for (int i = 0; i < (NB * REP) / THREADS; i++) hist1[t + i * THREADS] = 0u;
    if (t < NB) hist2[t] = 0u;
    __syncthreads();

    // ============ Level 1: replicated weighted histogram ============
    {
        const float inv1 = (float)NB / RANGE;
        #pragma unroll
        for (int k = 0; k < PPT; k += 2) {
            const int b0 = min(__float2int_rz(d2[k]     * inv1), NB - 1);
            const int b1 = min(__float2int_rz(d2[k + 1] * inv1), NB - 1);
            const bool same = (b0 == b1);      // adjacent points: usually same bin
            atomicAdd(&hist1[b0 * REP + rep], wi[k] + (same ? wi[k + 1] : 0u));
            if (!same)                          // predicated, no divergence split
                atomicAdd(&hist1[b1 * REP + rep], wi[k + 1]);
        }
    }
    __syncthreads();

    // Scan level-1 histogram (threads 0..127), find crossing bin.
    unsigned v1 = 0, h1 = 0;
    if (t < NB) {
        #pragma unroll
        for (int r = 0; r < REP; r++) h1 += hist1[t * REP + r];
        v1 = h1;                               // warp-inclusive scan
        #pragma unroll
        for (int o = 1; o < 32; o <<= 1) {
            const unsigned n = __shfl_up_sync(0xffffffffu, v1, o);
            if (lane >= o) v1 += n;
        }
        if (lane == 31) wtot[wid] = v1;
    }
    __syncthreads();

    const unsigned total = wtot[0] + wtot[1] + wtot[2] + wtot[3];
    unsigned target = (unsigned)(M0F * (float)total);

    if (t < NB) {
        unsigned off = 0;
        #pragma unroll
        for (int i = 0; i < 4; i++) if (i < wid) off += wtot[i];
        const unsigned cum = v1 + off;         // global inclusive prefix
        const unsigned bal = __ballot_sync(0xffffffffu, cum >= target);
        if (bal) {
            if (lane == __ffs(bal) - 1) { cbin[wid] = t; ccum[wid] = cum - h1; }
        } else if (lane == 0) {
            cbin[wid] = INT_MAX;
        }
    }
    __syncthreads();

    int bsel; unsigned csel;
    {
        bsel = cbin[0]; csel = ccum[0];
        if (cbin[1] < bsel) { bsel = cbin[1]; csel = ccum[1]; }
        if (cbin[2] < bsel) { bsel = cbin[2]; csel = ccum[2]; }
        if (cbin[3] < bsel) { bsel = cbin[3]; csel = ccum[3]; }
        if (bsel > NB - 1) bsel = NB - 1;
    }
    target -= csel;
    const float lo = (float)bsel * (RANGE / NB);
    __syncthreads();                            // wtot/cbin reuse in level 2

    // ============ Level 2: fine bins over [lo, lo + RANGE/NB) ============
    // Only ~N/NB points survive the range predicate -> atomics nearly free.
    {
        const float inv2 = (float)NB * (float)NB / RANGE;
        #pragma unroll
        for (int k = 0; k < PPT; k++) {
            const int bin = __float2int_rd((d2[k] - lo) * inv2);  // rd: no leak
            if ((unsigned)bin < (unsigned)NB) atomicAdd(&hist2[bin], wi[k]);
        }
    }
    __syncthreads();

    unsigned v2 = 0;
    if (t < NB) {
        v2 = hist2[t];
        #pragma unroll
        for (int o = 1; o < 32; o <<= 1) {
            const unsigned n = __shfl_up_sync(0xffffffffu, v2, o);
            if (lane >= o) v2 += n;
        }
        if (lane == 31) wtot[wid] = v2;
    }
    __syncthreads();

    if (t < NB) {
        unsigned off = 0;
        #pragma unroll
        for (int i = 0; i < 4; i++) if (i < wid) off += wtot[i];
        const unsigned bal = __ballot_sync(0xffffffffu, v2 + off >= target);
        if (bal) {
            if (lane == __ffs(bal) - 1) cbin[wid] = t;
        } else if (lane == 0) {
            cbin[wid] = INT_MAX;
        }
    }
    __syncthreads();

    int bsel2;
    {
        bsel2 = cbin[0];
        if (cbin[1] < bsel2) bsel2 = cbin[1];
        if (cbin[2] < bsel2) bsel2 = cbin[2];
        if (cbin[3] < bsel2) bsel2 = cbin[3];
        if (bsel2 > NB - 1) bsel2 = NB - 1;
    }
    // Threshold at center of selected fine bin: |t2 - t*| <= 3.7e-4 -> O(1e-7) err.
    const float t2 = lo + ((float)bsel2 + 0.5f) * (RANGE / (NB * NB));

    // ============ Epilogue: exact partial sums strictly below t2 ============
    float S = 0.f, Wl = 0.f;
    #pragma unroll
    for (int k = 0; k < PPT; k++) {
        if (d2[k] < t2) {
            const float wf = (float)wi[k] * INV_SCALE;
            S  = fmaf(d2[k], wf, S);
            Wl += wf;
        }
    }
    {
        const float rs = warp_sum(S);
        const float rw = warp_sum(Wl);
        if (lane == 0) { redS[wid] = rs; redW[wid] = rw; }
        __syncthreads();
        if (t == 0) {
            float Ss = 0.f, Ws = 0.f;
            #pragma unroll
            for (int i = 0; i < NW; i++) { Ss += redS[i]; Ws += redW[i]; }
            const float wb  = M0F * ((float)total * INV_SCALE);
            const float val = Ss + t2 * (wb - Ws);
            out[blk] = sqrtf(fmaxf(val, 0.f) / wb);
        }
    }
}

extern "C" void kernel_launch(void* const* d_in, const int* in_sizes, int n_in,
                              void* d_out, int out_size) {
    const float* input  = (const float*)d_in[0];   // (B, N, 2)
    const float* weight = (const float*)d_in[1];   // (B, N)
    const float* grid   = (const float*)d_in[2];   // (N, 2)
    float* out = (float*)d_out;                    // (B, N)

    const int total = in_sizes[1];                 // B * N queries (= out_size)
    dtm_kernel<<<total, THREADS>>>(input, weight, grid, out);
}

// round 8
// speedup vs baseline: 1.6559x; 1.1839x over previous
#include <cuda_runtime.h>
#include <climits>

// DTM layer via SINGLE-level 2048-bin weighted histogram quantile localization.
// Calibrated quadratic error law (err ~ C*Delta^2, C from R5 measurement) shows
// one level at NB=2048 (bin 5.9e-3, center eval) gives rel_err ~2e-5, 40x under
// the 1e-3 gate, while deleting the entire second histogram pass + scan.
// Weights quantized to u32 (x 2^19): deterministic integer histogram sums.

constexpr int   NPTS    = 4096;           // points per batch (H*W)
constexpr int   THREADS = 256;
constexpr int   PPT     = NPTS / THREADS; // 16 points/thread, register-resident
constexpr int   NW      = THREADS / 32;   // 8 warps
constexpr int   NB      = 2048;           // bins (single level)
constexpr int   BPT     = NB / THREADS;   // 8 bins per scan thread
constexpr float M0F     = 0.3f;
constexpr float RANGE   = 12.0f;          // safe upper bound on d2
constexpr float SCALE   = 524288.0f;      // 2^19: sum < 4096*2^19 = 2^31
constexpr float INV_SCALE = 1.0f / 524288.0f;

__device__ __forceinline__ float warp_sum(float v) {
    #pragma unroll
    for (int o = 16; o > 0; o >>= 1) v += __shfl_xor_sync(0xffffffffu, v, o);
    return v;
}

__global__ void __launch_bounds__(THREADS, 4) dtm_kernel(
    const float* __restrict__ input,   // (B, N, 2)
    const float* __restrict__ weight,  // (B, N)
    const float* __restrict__ grid,    // (N, 2)
    float* __restrict__ out)           // (B, N)
{
    __shared__ unsigned hist[NB];
    __shared__ unsigned wtot[NW];      // per-warp scan totals
    __shared__ int      cthr[NW];      // per-warp crossing-thread candidates
    __shared__ unsigned ccum[NW];      // cum weight before candidate's segment
    __shared__ float    redS[NW], redW[NW];

    const int blk  = blockIdx.x;              // b * NPTS + q
    const int b    = blk >> 12;                // NPTS == 4096
    const int q    = blk & (NPTS - 1);
    const int t    = threadIdx.x;
    const int lane = t & 31, wid = t >> 5;

    const float gx = __ldg(&grid[2 * q]);
    const float gy = __ldg(&grid[2 * q + 1]);

    const float4* __restrict__ pts4 =
        reinterpret_cast<const float4*>(input + (size_t)b * NPTS * 2);
    const float2* __restrict__ wgt2 =
        reinterpret_cast<const float2*>(weight + (size_t)b * NPTS);

    // Load 16 points/thread as 8 x float4 (2 points each) + 8 x float2 weights.
    float    d2[PPT];
    unsigned wi[PPT];
    #pragma unroll
    for (int k = 0; k < PPT / 2; k++) {
        const int u = t + k * THREADS;         // float4 index -> points 2u, 2u+1
        const float4 p = pts4[u];
        const float2 w = wgt2[u];
        float dx = p.x - gx, dy = p.y - gy;
        d2[2 * k]     = fmaf(dx, dx, dy * dy);
        dx = p.z - gx; dy = p.w - gy;
        d2[2 * k + 1] = fmaf(dx, dx, dy * dy);
        wi[2 * k]     = (unsigned)(w.x * SCALE);
        wi[2 * k + 1] = (unsigned)(w.y * SCALE);
    }

    // Zero histogram: 2048 words via 2 x STS.128 per thread.
    {
        const uint4 z = make_uint4(0u, 0u, 0u, 0u);
        reinterpret_cast<uint4*>(hist)[t]           = z;
        reinterpret_cast<uint4*>(hist)[t + THREADS] = z;
    }
    __syncthreads();

    // ============ Weighted histogram: 16 plain atomics/thread ============
    // 2048 bins + wide per-warp d2 spread -> conflict degree ~1 (spread ATOMS).
    {
        const float inv1 = (float)NB / RANGE;
        #pragma unroll
        for (int k = 0; k < PPT; k++) {
            const int bin = min(__float2int_rz(d2[k] * inv1), NB - 1);
            atomicAdd(&hist[bin], wi[k]);
        }
    }
    __syncthreads();

    // ============ Hierarchical scan + crossing-bin search ============
    // Each thread owns 8 consecutive bins [8t, 8t+8).
    const uint4 h0 = reinterpret_cast<const uint4*>(hist)[2 * t];
    const uint4 h1 = reinterpret_cast<const uint4*>(hist)[2 * t + 1];
    const unsigned seg = h0.x + h0.y + h0.z + h0.w + h1.x + h1.y + h1.z + h1.w;

    unsigned v = seg;                           // warp-inclusive scan of segments
    #pragma unroll
    for (int o = 1; o < 32; o <<= 1) {
        const unsigned n = __shfl_up_sync(0xffffffffu, v, o);
        if (lane >= o) v += n;
    }
    if (lane == 31) wtot[wid] = v;
    __syncthreads();

    unsigned total = 0, off = 0;
    #pragma unroll
    for (int i = 0; i < NW; i++) {
        const unsigned wv = wtot[i];
        total += wv;
        if (i < wid) off += wv;
    }
    const unsigned target = (unsigned)(M0F * (float)total);

    // First thread whose inclusive segment prefix reaches target.
    {
        const unsigned cum = v + off;
        const unsigned bal = __ballot_sync(0xffffffffu, cum >= target);
        if (bal) {
            if (lane == __ffs(bal) - 1) { cthr[wid] = t; ccum[wid] = cum - seg; }
        } else if (lane == 0) {
            cthr[wid] = INT_MAX;
        }
    }
    __syncthreads();

    int tsel = cthr[0]; unsigned csel = ccum[0];
    #pragma unroll
    for (int i = 1; i < NW; i++) {
        if (cthr[i] < tsel) { tsel = cthr[i]; csel = ccum[i]; }
    }
    if (tsel > THREADS - 1) tsel = THREADS - 1; // safety (cannot trigger)

    // Uniform walk inside the crossing segment (broadcast LDS, identical all threads).
    const uint4 g0 = reinterpret_cast<const uint4*>(hist)[2 * tsel];
    const uint4 g1 = reinterpret_cast<const uint4*>(hist)[2 * tsel + 1];
    int bin = tsel * BPT;
    {
        unsigned c = csel;
        const unsigned hv[8] = {g0.x, g0.y, g0.z, g0.w, g1.x, g1.y, g1.z, g1.w};
        #pragma unroll
        for (int j = 0; j < 7; j++) {
            if (c + hv[j] < target) { c += hv[j]; bin++; }
        }
    }

    // Threshold at bin center: |t2 - t*| <= RANGE/(2*NB) = 2.9e-3 -> ~2e-5 err.
    const float t2 = ((float)bin + 0.5f) * (RANGE / NB);

    // ============ Epilogue: exact partial sums strictly below t2 ============
    float S = 0.f, Wl = 0.f;
    #pragma unroll
    for (int k = 0; k < PPT; k++) {
        if (d2[k] < t2) {
            const float wf = (float)wi[k] * INV_SCALE;
            S  = fmaf(d2[k], wf, S);
            Wl += wf;
        }
    }
    {
        const float rs = warp_sum(S);
        const float rw = warp_sum(Wl);
        if (lane == 0) { redS[wid] = rs; redW[wid] = rw; }
        __syncthreads();
        if (t == 0) {
            float Ss = 0.f, Ws = 0.f;
            #pragma unroll
            for (int i = 0; i < NW; i++) { Ss += redS[i]; Ws += redW[i]; }
            const float wb  = M0F * ((float)total * INV_SCALE);
            const float val = Ss + t2 * (wb - Ws);
            out[blk] = sqrtf(fmaxf(val, 0.f) / wb);
        }
    }
}

extern "C" void kernel_launch(void* const* d_in, const int* in_sizes, int n_in,
                              void* d_out, int out_size) {
    const float* input  = (const float*)d_in[0];   // (B, N, 2)
    const float* weight = (const float*)d_in[1];   // (B, N)
    const float* grid   = (const float*)d_in[2];   // (N, 2)
    float* out = (float*)d_out;                    // (B, N)

    const int total = in_sizes[1];                 // B * N queries (= out_size)
    dtm_kernel<<<total, THREADS>>>(input, weight, grid, out);
}